// round 15
// baseline (speedup 1.0000x reference)
#include <cuda_runtime.h>
#include <cuda_fp16.h>
#include <math.h>
#include <stdint.h>

#define MAXN 50000
#define MAXE 500000
#define HMAX 4
#define HC_MAX 256
#define BMAX 1000
#define SCAN_T 1024

// ---------------- scratch ----------------------------------------------------
static __device__ __align__(16) __half g_hA[(size_t)MAXN * HC_MAX];
static __device__ __align__(16) __half g_hB[(size_t)MAXN * HC_MAX];
static __device__ __align__(16) float g_als[(size_t)MAXN * HMAX];
static __device__ __align__(16) float g_ald[(size_t)MAXN * HMAX];
static __device__ __align__(16) float g_xg[(size_t)BMAX * 64];
static __device__ float g_cnt[BMAX];
static __device__ __align__(16) float g_y1[(size_t)BMAX * 256];
static __device__ __align__(16) float g_y2[(size_t)BMAX * 256];
static __device__ int   g_src[MAXE];
static __device__ int   g_dst[MAXE];
static __device__ int   g_batch[MAXN];
static __device__ int   g_deg[MAXN];
static __device__ int   g_rowptr[MAXN + 1];
static __device__ int   g_cursor[MAXN];
static __device__ int   g_csrc[MAXE];
static __device__ int   g_is64;

// Pre-interleaved half2 weights: [Fin/2][Fout], entry = {W[2k][n], W[2k+1][n]}.
#define WOFF_W1  0
#define WOFF_W2  4096
#define WOFF_W3  36864
#define WOFF_WM1 45056
#define WOFF_WM2 53248
#define WTOTAL   86016
static __device__ __align__(16) __half2 g_Wh[WTOTAL];

static inline int cdiv(long long a, long long b) { return (int)((a + b - 1) / b); }

// ---------------- dtype probe (parallel) --------------------------------------
__global__ void detect_dtype(const void* ei_raw, int E, int N) {
    __shared__ int bad_s;
    if (threadIdx.x == 0) bad_s = 0;
    __syncthreads();
    const long long* p = (const long long*)ei_raw;
    int k = E < 256 ? E : 256;
    bool bad = false;
    for (int j = threadIdx.x; j < k; j += 256) {
        long long v = p[j];
        if (v < 0 || v >= N) bad = true;
    }
    if (bad) atomicOr(&bad_s, 1);
    __syncthreads();
    if (threadIdx.x == 0) g_is64 = bad_s ? 0 : 1;
}

// ---------------- fused setup: converts + zeroing + histograms ----------------
// Grid covers max(E, N*4, B*64). deg/cnt must be pre-zeroed (memsets).
__global__ void setup_kernel(const void* ei_raw, const void* b_raw,
                             int* __restrict__ src, int* __restrict__ dst,
                             int* __restrict__ deg,
                             int* __restrict__ batch, float* __restrict__ cnt,
                             float* __restrict__ als, float* __restrict__ ald,
                             float* __restrict__ xg, int E, int N, int B) {
    int i = blockIdx.x * blockDim.x + threadIdx.x;
    int is64 = g_is64;
    if (i < N * 4) { als[i] = 0.f; ald[i] = 0.f; }
    if (i < B * 64) xg[i] = 0.f;
    if (i < N) {
        int b;
        if (is64) b = (int)((const long long*)b_raw)[i];
        else      b = ((const int*)b_raw)[i];
        batch[i] = b;
        // warp-aggregated count (batch is sorted -> heavy same-address without this)
        unsigned act = __activemask();
        unsigned mask = __match_any_sync(act, b);
        int leader = __ffs(mask) - 1;
        if ((int)(threadIdx.x & 31) == leader)
            atomicAdd(&cnt[b], (float)__popc(mask));
    }
    if (i < E) {
        int s, d;
        if (is64) {
            const long long* p = (const long long*)ei_raw;
            s = (int)p[i]; d = (int)p[E + i];
        } else {
            const int* p = (const int*)ei_raw;
            s = p[i]; d = p[E + i];
        }
        src[i] = s; dst[i] = d;
        atomicAdd(&deg[d], 1);
    }
}

// One-shot: convert all weight matrices to interleaved half2.
__global__ void convert_all_w(const float* __restrict__ W1, const float* __restrict__ W2,
                              const float* __restrict__ W3, const float* __restrict__ Wm1,
                              const float* __restrict__ Wm2, __half2* __restrict__ out) {
    int i = blockIdx.x * blockDim.x + threadIdx.x;
    if (i >= WTOTAL) return;
    const float* W; int Fout, base;
    if (i < WOFF_W2)       { W = W1;  Fout = 256; base = WOFF_W1; }
    else if (i < WOFF_W3)  { W = W2;  Fout = 256; base = WOFF_W2; }
    else if (i < WOFF_WM1) { W = W3;  Fout = 64;  base = WOFF_W3; }
    else if (i < WOFF_WM2) { W = Wm1; Fout = 256; base = WOFF_WM1; }
    else                   { W = Wm2; Fout = 256; base = WOFF_WM2; }
    int j = i - base;
    int kp = j / Fout, n = j - kp * Fout;
    out[i] = __floats2half2_rn(W[(size_t)(2 * kp) * Fout + n],
                               W[(size_t)(2 * kp + 1) * Fout + n]);
}

// ---------------- single-kernel exclusive scan (1 block) ----------------------
__global__ void scan_all(const int* __restrict__ deg, int* __restrict__ rowptr,
                         int* __restrict__ cursor, int n, int E) {
    __shared__ int s[SCAN_T];
    const int K = (n + SCAN_T - 1) / SCAN_T;
    int tid = threadIdx.x;
    int base = tid * K;
    int sum = 0;
    for (int j = 0; j < K; j++) {
        int idx = base + j;
        sum += (idx < n) ? deg[idx] : 0;
    }
    s[tid] = sum; __syncthreads();
    for (int off = 1; off < SCAN_T; off <<= 1) {
        int t = (tid >= off) ? s[tid - off] : 0;
        __syncthreads();
        s[tid] += t;
        __syncthreads();
    }
    int run = (tid > 0) ? s[tid - 1] : 0;
    for (int j = 0; j < K; j++) {
        int idx = base + j;
        if (idx < n) {
            rowptr[idx] = run;
            cursor[idx] = run;
            run += deg[idx];
        }
    }
    if (tid == 0) rowptr[n] = E;
}

__global__ void scatter_kernel(const int* __restrict__ srcA, const int* __restrict__ dstA,
                               int* __restrict__ cursor, int* __restrict__ csrc, int E) {
    int i = blockIdx.x * blockDim.x + threadIdx.x;
    if (i >= E) return;
    int pos = atomicAdd(&cursor[dstA[i]], 1);
    csrc[pos] = srcA[i];
}

// ---------------- FP16 tensor-core GEMM (m16n8k16, fp32 accum) ---------------
__device__ __forceinline__ void mma_f16(float* c, const uint32_t* a, const uint32_t* b) {
    asm volatile(
        "mma.sync.aligned.m16n8k16.row.col.f32.f16.f16.f32 "
        "{%0,%1,%2,%3}, {%4,%5,%6,%7}, {%8,%9}, {%0,%1,%2,%3};"
        : "+f"(c[0]), "+f"(c[1]), "+f"(c[2]), "+f"(c[3])
        : "r"(a[0]), "r"(a[1]), "r"(a[2]), "r"(a[3]), "r"(b[0]), "r"(b[1]));
}

__device__ __forceinline__ float4 ld4(const float* p) { return *(const float4*)p; }
__device__ __forceinline__ float4 ld4(const __half* p) {
    const __half2* h = (const __half2*)p;
    float2 a = __half22float2(h[0]), b = __half22float2(h[1]);
    return make_float4(a.x, a.y, b.x, b.y);
}
__device__ __forceinline__ void st2(float* p, float a, float b) {
    *(float2*)p = make_float2(a, b);
}
__device__ __forceinline__ void st2(__half* p, float a, float b) {
    *(__half2*)p = __floats2half2_rn(a, b);
}

template <typename TI, typename TO, int BN, int WR, int WC, int MI>
__global__ void __launch_bounds__(256)
hgemm(const TI* __restrict__ X, const __half2* __restrict__ Wh,
      TO* __restrict__ out, int N, int Fin, int Fout,
      const float* __restrict__ abias, int arelu,
      const float* __restrict__ asrc, const float* __restrict__ adst,
      float* __restrict__ als, float* __restrict__ ald, int Hn) {
    constexpr int BM = 128, BK = 32, NI = 4;
    constexpr int WM = BM / WR;
    constexpr int WN = BN / WC;
    constexpr int AP = BK + 8;
    constexpr int BP = BN + 4;
    __shared__ __half  As[BM][AP];
    __shared__ __half2 Bs2[BK / 2][BP];
    const int tx = threadIdx.x;
    const int n0 = blockIdx.x * BM;
    const int j0 = blockIdx.y * BN;
    const int w  = tx >> 5;
    const int lane = tx & 31;
    const int g = lane >> 2;
    const int q = lane & 3;
    const int wr = w / WC, wc = w % WC;
    const int m0w = wr * WM, n0w = wc * WN;

    float acc[MI][NI][4];
#pragma unroll
    for (int mi = 0; mi < MI; mi++)
#pragma unroll
        for (int ni = 0; ni < NI; ni++)
#pragma unroll
            for (int t = 0; t < 4; t++) acc[mi][ni][t] = 0.f;

    const int ar  = tx >> 1;
    const int ac0 = (tx & 1) * 16;
    const int brr = tx & 15;
    const int bgp = tx >> 4;
    constexpr int BCOLS = BN / 16;

    for (int k0 = 0; k0 < Fin; k0 += BK) {
        {
            int n = n0 + ar;
            __half2 hbuf[8];
#pragma unroll
            for (int i = 0; i < 4; i++) {
                int c = ac0 + i * 4;
                float4 v = make_float4(0.f, 0.f, 0.f, 0.f);
                if (n < N) {
                    v = ld4(&X[(size_t)n * Fin + k0 + c]);
                    if (abias) {
                        const float4 b = *(const float4*)&abias[k0 + c];
                        v.x += b.x; v.y += b.y; v.z += b.z; v.w += b.w;
                        if (arelu) {
                            v.x = fmaxf(v.x, 0.f); v.y = fmaxf(v.y, 0.f);
                            v.z = fmaxf(v.z, 0.f); v.w = fmaxf(v.w, 0.f);
                        }
                    }
                }
                hbuf[i * 2 + 0] = __floats2half2_rn(v.x, v.y);
                hbuf[i * 2 + 1] = __floats2half2_rn(v.z, v.w);
            }
            uint4* dst = (uint4*)&As[ar][ac0];
            dst[0] = ((uint4*)hbuf)[0];
            dst[1] = ((uint4*)hbuf)[1];
        }
        {
            const __half2* wrow = Wh + (size_t)(k0 / 2 + brr) * Fout + j0;
#pragma unroll
            for (int i = 0; i < BCOLS / 4; i++) {
                int c = bgp * BCOLS + i * 4;
                *(uint4*)&Bs2[brr][c] = *(const uint4*)&wrow[c];
            }
        }
        __syncthreads();
#pragma unroll
        for (int ks = 0; ks < 2; ks++) {
            uint32_t af[MI][4], bf[NI][2];
#pragma unroll
            for (int mi = 0; mi < MI; mi++) {
                int m = m0w + mi * 16 + g;
                const uint32_t* r0 = (const uint32_t*)&As[m][ks * 16];
                const uint32_t* r1 = (const uint32_t*)&As[m + 8][ks * 16];
                af[mi][0] = r0[q];
                af[mi][1] = r1[q];
                af[mi][2] = r0[q + 4];
                af[mi][3] = r1[q + 4];
            }
#pragma unroll
            for (int ni = 0; ni < NI; ni++) {
                int c = n0w + ni * 8 + g;
                bf[ni][0] = *(const uint32_t*)&Bs2[ks * 8 + q][c];
                bf[ni][1] = *(const uint32_t*)&Bs2[ks * 8 + q + 4][c];
            }
#pragma unroll
            for (int mi = 0; mi < MI; mi++)
#pragma unroll
                for (int ni = 0; ni < NI; ni++)
                    mma_f16(acc[mi][ni], af[mi], bf[ni]);
        }
        __syncthreads();
    }
#pragma unroll
    for (int mi = 0; mi < MI; mi++) {
        int r0 = n0 + m0w + mi * 16 + g;
        int r1 = r0 + 8;
#pragma unroll
        for (int ni = 0; ni < NI; ni++) {
            int c = j0 + n0w + ni * 8 + 2 * q;
            if (r0 < N) st2(&out[(size_t)r0 * Fout + c], acc[mi][ni][0], acc[mi][ni][1]);
            if (r1 < N) st2(&out[(size_t)r1 * Fout + c], acc[mi][ni][2], acc[mi][ni][3]);
        }
    }
    if (asrc) {
        int hh = (j0 + n0w) >> 6;
        float as_[4][2], ad_[4][2];
#pragma unroll
        for (int ni = 0; ni < NI; ni++) {
            int cc = ((j0 + n0w + ni * 8 + 2 * q) & 63);
            as_[ni][0] = asrc[hh * 64 + cc];
            as_[ni][1] = asrc[hh * 64 + cc + 1];
            ad_[ni][0] = adst[hh * 64 + cc];
            ad_[ni][1] = adst[hh * 64 + cc + 1];
        }
#pragma unroll
        for (int mi = 0; mi < MI; mi++) {
            float s0 = 0.f, d0 = 0.f, s1 = 0.f, d1 = 0.f;
#pragma unroll
            for (int ni = 0; ni < NI; ni++) {
                s0 += acc[mi][ni][0] * as_[ni][0] + acc[mi][ni][1] * as_[ni][1];
                d0 += acc[mi][ni][0] * ad_[ni][0] + acc[mi][ni][1] * ad_[ni][1];
                s1 += acc[mi][ni][2] * as_[ni][0] + acc[mi][ni][3] * as_[ni][1];
                d1 += acc[mi][ni][2] * ad_[ni][0] + acc[mi][ni][3] * ad_[ni][1];
            }
#pragma unroll
            for (int off = 1; off <= 2; off <<= 1) {
                s0 += __shfl_xor_sync(0xFFFFFFFFu, s0, off);
                d0 += __shfl_xor_sync(0xFFFFFFFFu, d0, off);
                s1 += __shfl_xor_sync(0xFFFFFFFFu, s1, off);
                d1 += __shfl_xor_sync(0xFFFFFFFFu, d1, off);
            }
            if (q == 0) {
                int r0 = n0 + m0w + mi * 16 + g;
                int r1 = r0 + 8;
                if (r0 < N) { atomicAdd(&als[r0 * Hn + hh], s0);
                              atomicAdd(&ald[r0 * Hn + hh], d0); }
                if (r1 < N) { atomicAdd(&als[r1 * Hn + hh], s1);
                              atomicAdd(&ald[r1 * Hn + hh], d1); }
            }
        }
    }
}

template <typename TI, typename TO>
static void launch_gemm(const TI* X, const __half2* Wh, TO* out,
                        int N, int Fin, int Fout, const float* abias, int arelu,
                        const float* asrc, const float* adst,
                        float* als, float* ald) {
    int Hn = Fout / 64;
    if (Fout % 128 == 0) {
        dim3 grid(cdiv(N, 128), Fout / 128);
        hgemm<TI, TO, 128, 2, 4, 4><<<grid, 256>>>(X, Wh, out, N, Fin, Fout, abias,
                                                   arelu, asrc, adst, als, ald, Hn);
    } else {
        dim3 grid(cdiv(N, 128), Fout / 64);
        hgemm<TI, TO, 64, 4, 2, 2><<<grid, 256>>>(X, Wh, out, N, Fin, Fout, abias,
                                                  arelu, asrc, adst, als, ald, Hn);
    }
}

// ---------------- fused GAT helpers ------------------------------------------
__device__ __forceinline__ float lrelu(float x) { return (x > 0.f) ? x : 0.2f * x; }

__device__ __forceinline__ void softstep(float m, float e, float& s, float& p, float& mn) {
    float d = m - e;
    float ex = __expf(-fabsf(d));
    s = (d < 0.f) ? ex : 1.f;
    p = (d < 0.f) ? 1.f : ex;
    mn = fmaxf(m, e);
}

__device__ __forceinline__ float sel4(float4 a, int h) {
    float lo = (h & 1) ? a.y : a.x;
    float hi = (h & 1) ? a.w : a.z;
    return (h & 2) ? hi : lo;
}

// ---- H=4, lane-sliced: lane i owns 8 contiguous halves of head i/8 ----------
__global__ void gat4_sliced(const int* __restrict__ rowptr, const int* __restrict__ csrc,
                            const __half* __restrict__ hlin,
                            const float* __restrict__ als, const float* __restrict__ ald,
                            __half* __restrict__ out, int N) {
    int n = (blockIdx.x * blockDim.x + threadIdx.x) >> 5;
    int lane = threadIdx.x & 31;
    if (n >= N) return;
    const int h = lane >> 3;

    float aldv = ald[n * 4 + h];
    float4 a4 = *((const float4*)als + n);
    float m = lrelu(sel4(a4, h) + aldv);       // self loop
    float z = 1.f;

    float acc[8];
    {
        uint4 u = *(const uint4*)(hlin + (size_t)n * 256 + lane * 8);
        float2 t0 = __half22float2(*(__half2*)&u.x);
        float2 t1 = __half22float2(*(__half2*)&u.y);
        float2 t2 = __half22float2(*(__half2*)&u.z);
        float2 t3 = __half22float2(*(__half2*)&u.w);
        acc[0] = t0.x; acc[1] = t0.y; acc[2] = t1.x; acc[3] = t1.y;
        acc[4] = t2.x; acc[5] = t2.y; acc[6] = t3.x; acc[7] = t3.y;
    }

    int beg = rowptr[n], end = rowptr[n + 1];
    int src = 0; float e = 0.f;
    if (beg < end) {
        src = csrc[beg];
        float4 s4 = __ldg((const float4*)als + src);
        e = lrelu(sel4(s4, h) + aldv);
    }
    for (int k = beg; k < end; k++) {
        int csrc_cur = src; float e_cur = e;
        if (k + 1 < end) {
            src = csrc[k + 1];
            float4 s4 = __ldg((const float4*)als + src);
            e = lrelu(sel4(s4, h) + aldv);
        }
        uint4 u = *(const uint4*)(hlin + (size_t)csrc_cur * 256 + lane * 8);
        float s, p, mn;
        softstep(m, e_cur, s, p, mn);
        float2 t0 = __half22float2(*(__half2*)&u.x);
        float2 t1 = __half22float2(*(__half2*)&u.y);
        float2 t2 = __half22float2(*(__half2*)&u.z);
        float2 t3 = __half22float2(*(__half2*)&u.w);
        acc[0] = acc[0] * s + p * t0.x; acc[1] = acc[1] * s + p * t0.y;
        acc[2] = acc[2] * s + p * t1.x; acc[3] = acc[3] * s + p * t1.y;
        acc[4] = acc[4] * s + p * t2.x; acc[5] = acc[5] * s + p * t2.y;
        acc[6] = acc[6] * s + p * t3.x; acc[7] = acc[7] * s + p * t3.y;
        z = z * s + p;
        m = mn;
    }
    float inv = 1.f / (z + 1e-16f);
    uint4 o;
    *(__half2*)&o.x = __floats2half2_rn(acc[0] * inv, acc[1] * inv);
    *(__half2*)&o.y = __floats2half2_rn(acc[2] * inv, acc[3] * inv);
    *(__half2*)&o.z = __floats2half2_rn(acc[4] * inv, acc[5] * inv);
    *(__half2*)&o.w = __floats2half2_rn(acc[6] * inv, acc[7] * inv);
    *(uint4*)(out + (size_t)n * 256 + lane * 8) = o;
}

// ---- H=1 with fused mean-pool accumulate (+bias) into xg --------------------
__global__ void gat1_pool(const int* __restrict__ rowptr, const int* __restrict__ csrc,
                          const __half* __restrict__ hlin,
                          const float* __restrict__ als, const float* __restrict__ ald,
                          int N, const int* __restrict__ batch,
                          const float* __restrict__ bias, float* __restrict__ xg) {
    int n = (blockIdx.x * blockDim.x + threadIdx.x) >> 5;
    int lane = threadIdx.x & 31;
    if (n >= N) return;

    float aldv = ald[n];
    float m = lrelu(als[n] + aldv);
    float z = 1.f;
    float2 acc = __half22float2(((const __half2*)(hlin + (size_t)n * 64))[lane]);

    int beg = rowptr[n], end = rowptr[n + 1];
    int src = 0; float e = 0.f;
    if (beg < end) {
        src = csrc[beg];
        e = lrelu(als[src] + aldv);
    }
    for (int k = beg; k < end; k++) {
        int cur = src; float e_cur = e;
        if (k + 1 < end) {
            src = csrc[k + 1];
            e = lrelu(als[src] + aldv);
        }
        __half2 f = ((const __half2*)(hlin + (size_t)cur * 64))[lane];
        float s, p, mn;
        softstep(m, e_cur, s, p, mn);
        float2 fv = __half22float2(f);
        acc.x = acc.x * s + p * fv.x;
        acc.y = acc.y * s + p * fv.y;
        z = z * s + p;
        m = mn;
    }
    float inv = 1.f / (z + 1e-16f);
    int b = batch[n];
    atomicAdd(&xg[b * 64 + 2 * lane],     acc.x * inv + bias[2 * lane]);
    atomicAdd(&xg[b * 64 + 2 * lane + 1], acc.y * inv + bias[2 * lane + 1]);
}

// ---------------- pooling divide + LN ----------------------------------------
__global__ void pool_div(float* __restrict__ xg, const float* __restrict__ cnt, int B) {
    int t = blockIdx.x * blockDim.x + threadIdx.x;
    if (t >= B * 64) return;
    xg[t] /= fmaxf(cnt[t >> 6], 1.f);
}

__global__ void bias_ln(const float* __restrict__ y, const float* __restrict__ bias,
                        const float* __restrict__ g, const float* __restrict__ be,
                        float* __restrict__ out, int Fn) {
    __shared__ float red[256];
    int b = blockIdx.x, j = threadIdx.x;
    float v = y[(size_t)b * Fn + j] + bias[j];
    red[j] = v; __syncthreads();
#pragma unroll
    for (int s = 128; s > 0; s >>= 1) { if (j < s) red[j] += red[j + s]; __syncthreads(); }
    float mu = red[0] * (1.f / 256.f);
    __syncthreads();
    float dv = v - mu;
    red[j] = dv * dv; __syncthreads();
#pragma unroll
    for (int s = 128; s > 0; s >>= 1) { if (j < s) red[j] += red[j + s]; __syncthreads(); }
    float var = red[0] * (1.f / 256.f);
    out[(size_t)b * Fn + j] = dv * rsqrtf(var + 1e-5f) * g[j] + be[j];
}

// ---------------- host orchestration ---------------------------------------
extern "C" void kernel_launch(void* const* d_in, const int* in_sizes, int n_in,
                              void* d_out, int out_size) {
    const float* x      = (const float*)d_in[0];
    const void*  ei_raw = d_in[1];
    const void*  b_raw  = d_in[2];
    const float* W1  = (const float*)d_in[3];
    const float* as1 = (const float*)d_in[4];
    const float* ad1 = (const float*)d_in[5];
    const float* b1  = (const float*)d_in[6];
    const float* W2  = (const float*)d_in[7];
    const float* as2 = (const float*)d_in[8];
    const float* ad2 = (const float*)d_in[9];
    const float* b2  = (const float*)d_in[10];
    const float* W3  = (const float*)d_in[11];
    const float* as3 = (const float*)d_in[12];
    const float* ad3 = (const float*)d_in[13];
    const float* b3  = (const float*)d_in[14];
    const float* Wm1 = (const float*)d_in[15];
    const float* bm1 = (const float*)d_in[16];
    const float* Wm2 = (const float*)d_in[17];
    const float* bm2 = (const float*)d_in[18];
    const float* g2  = (const float*)d_in[19];
    const float* be2 = (const float*)d_in[20];

    int N = in_sizes[0] / 32;
    int E = in_sizes[1] / 2;
    int B = out_size / 256;

    __half *hA, *hB;
    __half2 *Wh;
    float *als, *ald, *xg, *cnt, *y1, *y2;
    int *srcA, *dstA, *batch, *deg, *rowptr, *cursor, *csrc;
    cudaGetSymbolAddress((void**)&hA,   g_hA);
    cudaGetSymbolAddress((void**)&hB,   g_hB);
    cudaGetSymbolAddress((void**)&Wh,   g_Wh);
    cudaGetSymbolAddress((void**)&als,  g_als);
    cudaGetSymbolAddress((void**)&ald,  g_ald);
    cudaGetSymbolAddress((void**)&xg,   g_xg);
    cudaGetSymbolAddress((void**)&cnt,  g_cnt);
    cudaGetSymbolAddress((void**)&y1,   g_y1);
    cudaGetSymbolAddress((void**)&y2,   g_y2);
    cudaGetSymbolAddress((void**)&srcA, g_src);
    cudaGetSymbolAddress((void**)&dstA, g_dst);
    cudaGetSymbolAddress((void**)&batch, g_batch);
    cudaGetSymbolAddress((void**)&deg,  g_deg);
    cudaGetSymbolAddress((void**)&rowptr, g_rowptr);
    cudaGetSymbolAddress((void**)&cursor, g_cursor);
    cudaGetSymbolAddress((void**)&csrc, g_csrc);

    // preprocessing: dtype probe, weight conversion, fused setup
    detect_dtype<<<1, 256>>>(ei_raw, E, N);
    convert_all_w<<<cdiv(WTOTAL, 256), 256>>>(W1, W2, W3, Wm1, Wm2, Wh);
    cudaMemsetAsync(deg, 0, (size_t)N * sizeof(int));
    cudaMemsetAsync(cnt, 0, (size_t)B * sizeof(float));
    {
        long long tot = E;                      // E > N*4 and E > B*64 here
        if ((long long)N * 4 > tot) tot = (long long)N * 4;
        if ((long long)B * 64 > tot) tot = (long long)B * 64;
        setup_kernel<<<cdiv(tot, 256), 256>>>(ei_raw, b_raw, srcA, dstA, deg,
                                              batch, cnt, als, ald, xg, E, N, B);
    }

    // conv1 GEMM
    launch_gemm<float, __half>(x, Wh + WOFF_W1, hA, N, 32, 256, nullptr, 0,
                               as1, ad1, als, ald);

    // CSR by dst (single-kernel scan + scatter)
    scan_all<<<1, SCAN_T>>>(deg, rowptr, cursor, N, E);
    scatter_kernel<<<cdiv(E, 256), 256>>>(srcA, dstA, cursor, csrc, E);

    // conv1 aggregate (lane-sliced)
    gat4_sliced<<<cdiv((long long)N * 32, 256), 256>>>(rowptr, csrc, hA, als, ald, hB, N);
    // conv2
    cudaMemsetAsync(als, 0, (size_t)N * 4 * sizeof(float));
    cudaMemsetAsync(ald, 0, (size_t)N * 4 * sizeof(float));
    launch_gemm<__half, __half>(hB, Wh + WOFF_W2, hA, N, 256, 256, b1, 1,
                                as2, ad2, als, ald);
    gat4_sliced<<<cdiv((long long)N * 32, 256), 256>>>(rowptr, csrc, hA, als, ald, hB, N);
    // conv3 (H=1) + fused mean-pool accumulate (+b3)
    cudaMemsetAsync(als, 0, (size_t)N * sizeof(float));
    cudaMemsetAsync(ald, 0, (size_t)N * sizeof(float));
    launch_gemm<__half, __half>(hB, Wh + WOFF_W3, hA, N, 256, 64, b2, 1,
                                as3, ad3, als, ald);
    gat1_pool<<<cdiv((long long)N * 32, 256), 256>>>(rowptr, csrc, hA, als, ald,
                                                     N, batch, b3, xg);
    pool_div<<<cdiv(B * 64, 256), 256>>>(xg, cnt, B);

    // MLP head (fp32 in/out)
    launch_gemm<float, float>(xg, Wh + WOFF_WM1, y1, B, 64, 256, nullptr, 0,
                              nullptr, nullptr, nullptr, nullptr);
    launch_gemm<float, float>(y1, Wh + WOFF_WM2, y2, B, 256, 256, bm1, 1,
                              nullptr, nullptr, nullptr, nullptr);
    bias_ln<<<B, 256>>>(y2, bm2, g2, be2, (float*)d_out, 256);
}

// round 16
// speedup vs baseline: 1.1902x; 1.1902x over previous
#include <cuda_runtime.h>
#include <cuda_fp16.h>
#include <math.h>
#include <stdint.h>

#define MAXN 50000
#define MAXE 500000
#define HMAX 4
#define HC_MAX 256
#define BMAX 1000
#define SCAN_T 1024

// ---------------- scratch ----------------------------------------------------
static __device__ __align__(16) __half g_hA[(size_t)MAXN * HC_MAX];
static __device__ __align__(16) __half g_hB[(size_t)MAXN * HC_MAX];
static __device__ __align__(16) float g_als[(size_t)MAXN * HMAX];
static __device__ __align__(16) float g_ald[(size_t)MAXN * HMAX];
static __device__ __align__(16) float g_xg[(size_t)BMAX * 64];
static __device__ float g_cnt[BMAX];
static __device__ __align__(16) float g_y1[(size_t)BMAX * 256];
static __device__ __align__(16) float g_y2[(size_t)BMAX * 256];
static __device__ int   g_src[MAXE];
static __device__ int   g_dst[MAXE];
static __device__ int   g_batch[MAXN];
static __device__ int   g_deg[MAXN];
static __device__ int   g_excl[MAXN];
static __device__ int   g_bsum[SCAN_T];
static __device__ int   g_rowptr[MAXN + 1];
static __device__ int   g_cursor[MAXN];
static __device__ int   g_csrc[MAXE];
static __device__ int   g_is64;

// Pre-interleaved half2 weights: [Fin/2][Fout], entry = {W[2k][n], W[2k+1][n]}.
#define WOFF_W1  0
#define WOFF_W2  4096
#define WOFF_W3  36864
#define WOFF_WM1 45056
#define WOFF_WM2 53248
#define WTOTAL   86016
static __device__ __align__(16) __half2 g_Wh[WTOTAL];

static inline int cdiv(long long a, long long b) { return (int)((a + b - 1) / b); }

// ---------------- dtype probe (parallel) --------------------------------------
__global__ void detect_dtype(const void* ei_raw, int E, int N) {
    __shared__ int bad_s;
    if (threadIdx.x == 0) bad_s = 0;
    __syncthreads();
    const long long* p = (const long long*)ei_raw;
    int k = E < 256 ? E : 256;
    bool bad = false;
    for (int j = threadIdx.x; j < k; j += 256) {
        long long v = p[j];
        if (v < 0 || v >= N) bad = true;
    }
    if (bad) atomicOr(&bad_s, 1);
    __syncthreads();
    if (threadIdx.x == 0) g_is64 = bad_s ? 0 : 1;
}

__global__ void convert_ei(const void* ei_raw, int* __restrict__ src,
                           int* __restrict__ dst, int* __restrict__ deg, int E) {
    int i = blockIdx.x * blockDim.x + threadIdx.x;
    if (i >= E) return;
    int s, d;
    if (g_is64) {
        const long long* p = (const long long*)ei_raw;
        s = (int)p[i]; d = (int)p[E + i];
    } else {
        const int* p = (const int*)ei_raw;
        s = p[i]; d = p[E + i];
    }
    src[i] = s; dst[i] = d;
    atomicAdd(&deg[d], 1);
}

// convert batch + warp-aggregated counts (batch is sorted by construction)
__global__ void convert_batch(const void* b_raw, int* __restrict__ out,
                              float* __restrict__ cnt, int N) {
    int i = blockIdx.x * blockDim.x + threadIdx.x;
    if (i >= N) return;
    int b;
    if (g_is64) b = (int)((const long long*)b_raw)[i];
    else        b = ((const int*)b_raw)[i];
    out[i] = b;
    unsigned act = __activemask();
    unsigned mask = __match_any_sync(act, b);
    int leader = __ffs(mask) - 1;
    if ((int)(threadIdx.x & 31) == leader)
        atomicAdd(&cnt[b], (float)__popc(mask));
}

// One-shot: convert all weight matrices to interleaved half2.
__global__ void convert_all_w(const float* __restrict__ W1, const float* __restrict__ W2,
                              const float* __restrict__ W3, const float* __restrict__ Wm1,
                              const float* __restrict__ Wm2, __half2* __restrict__ out) {
    int i = blockIdx.x * blockDim.x + threadIdx.x;
    if (i >= WTOTAL) return;
    const float* W; int Fout, base;
    if (i < WOFF_W2)       { W = W1;  Fout = 256; base = WOFF_W1; }
    else if (i < WOFF_W3)  { W = W2;  Fout = 256; base = WOFF_W2; }
    else if (i < WOFF_WM1) { W = W3;  Fout = 64;  base = WOFF_W3; }
    else if (i < WOFF_WM2) { W = Wm1; Fout = 256; base = WOFF_WM1; }
    else                   { W = Wm2; Fout = 256; base = WOFF_WM2; }
    int j = i - base;
    int kp = j / Fout, n = j - kp * Fout;
    out[i] = __floats2half2_rn(W[(size_t)(2 * kp) * Fout + n],
                               W[(size_t)(2 * kp + 1) * Fout + n]);
}

// ---------------- CSR build (round-14 3-stage scan) ---------------------------
__global__ void scan1(const int* __restrict__ deg, int* __restrict__ excl,
                      int* __restrict__ bsum, int n) {
    __shared__ int s[SCAN_T];
    int i = blockIdx.x * SCAN_T + threadIdx.x;
    int v = (i < n) ? deg[i] : 0;
    s[threadIdx.x] = v; __syncthreads();
    for (int off = 1; off < SCAN_T; off <<= 1) {
        int t = (threadIdx.x >= off) ? s[threadIdx.x - off] : 0;
        __syncthreads();
        s[threadIdx.x] += t;
        __syncthreads();
    }
    if (i < n) excl[i] = s[threadIdx.x] - v;
    if (threadIdx.x == SCAN_T - 1) bsum[blockIdx.x] = s[SCAN_T - 1];
}

__global__ void scan2(int* __restrict__ bsum, int nb) {
    __shared__ int s[SCAN_T];
    int v = (threadIdx.x < nb) ? bsum[threadIdx.x] : 0;
    s[threadIdx.x] = v; __syncthreads();
    for (int off = 1; off < SCAN_T; off <<= 1) {
        int t = (threadIdx.x >= off) ? s[threadIdx.x - off] : 0;
        __syncthreads();
        s[threadIdx.x] += t;
        __syncthreads();
    }
    if (threadIdx.x < nb) bsum[threadIdx.x] = s[threadIdx.x] - v;
}

__global__ void scan3(const int* __restrict__ excl, const int* __restrict__ bsum,
                      int* __restrict__ rowptr, int* __restrict__ cursor, int n, int E) {
    int i = blockIdx.x * blockDim.x + threadIdx.x;
    if (i < n) { int r = excl[i] + bsum[i / SCAN_T]; rowptr[i] = r; cursor[i] = r; }
    if (i == 0) rowptr[n] = E;
}

__global__ void scatter_kernel(const int* __restrict__ srcA, const int* __restrict__ dstA,
                               int* __restrict__ cursor, int* __restrict__ csrc, int E) {
    int i = blockIdx.x * blockDim.x + threadIdx.x;
    if (i >= E) return;
    int pos = atomicAdd(&cursor[dstA[i]], 1);
    csrc[pos] = srcA[i];
}

// ---------------- FP16 tensor-core GEMM (m16n8k16, fp32 accum) ---------------
__device__ __forceinline__ void mma_f16(float* c, const uint32_t* a, const uint32_t* b) {
    asm volatile(
        "mma.sync.aligned.m16n8k16.row.col.f32.f16.f16.f32 "
        "{%0,%1,%2,%3}, {%4,%5,%6,%7}, {%8,%9}, {%0,%1,%2,%3};"
        : "+f"(c[0]), "+f"(c[1]), "+f"(c[2]), "+f"(c[3])
        : "r"(a[0]), "r"(a[1]), "r"(a[2]), "r"(a[3]), "r"(b[0]), "r"(b[1]));
}

__device__ __forceinline__ float4 ld4(const float* p) { return *(const float4*)p; }
__device__ __forceinline__ float4 ld4(const __half* p) {
    const __half2* h = (const __half2*)p;
    float2 a = __half22float2(h[0]), b = __half22float2(h[1]);
    return make_float4(a.x, a.y, b.x, b.y);
}
__device__ __forceinline__ void st2(float* p, float a, float b) {
    *(float2*)p = make_float2(a, b);
}
__device__ __forceinline__ void st2(__half* p, float a, float b) {
    *(__half2*)p = __floats2half2_rn(a, b);
}

template <typename TI, typename TO, int BN, int WR, int WC, int MI>
__global__ void __launch_bounds__(256)
hgemm(const TI* __restrict__ X, const __half2* __restrict__ Wh,
      TO* __restrict__ out, int N, int Fin, int Fout,
      const float* __restrict__ abias, int arelu,
      const float* __restrict__ asrc, const float* __restrict__ adst,
      float* __restrict__ als, float* __restrict__ ald, int Hn) {
    constexpr int BM = 128, BK = 32, NI = 4;
    constexpr int WM = BM / WR;
    constexpr int WN = BN / WC;
    constexpr int AP = BK + 8;
    constexpr int BP = BN + 4;
    __shared__ __half  As[BM][AP];
    __shared__ __half2 Bs2[BK / 2][BP];
    const int tx = threadIdx.x;
    const int n0 = blockIdx.x * BM;
    const int j0 = blockIdx.y * BN;
    const int w  = tx >> 5;
    const int lane = tx & 31;
    const int g = lane >> 2;
    const int q = lane & 3;
    const int wr = w / WC, wc = w % WC;
    const int m0w = wr * WM, n0w = wc * WN;

    float acc[MI][NI][4];
#pragma unroll
    for (int mi = 0; mi < MI; mi++)
#pragma unroll
        for (int ni = 0; ni < NI; ni++)
#pragma unroll
            for (int t = 0; t < 4; t++) acc[mi][ni][t] = 0.f;

    const int ar  = tx >> 1;
    const int ac0 = (tx & 1) * 16;
    const int brr = tx & 15;
    const int bgp = tx >> 4;
    constexpr int BCOLS = BN / 16;

    for (int k0 = 0; k0 < Fin; k0 += BK) {
        {
            int n = n0 + ar;
            __half2 hbuf[8];
#pragma unroll
            for (int i = 0; i < 4; i++) {
                int c = ac0 + i * 4;
                float4 v = make_float4(0.f, 0.f, 0.f, 0.f);
                if (n < N) {
                    v = ld4(&X[(size_t)n * Fin + k0 + c]);
                    if (abias) {
                        const float4 b = *(const float4*)&abias[k0 + c];
                        v.x += b.x; v.y += b.y; v.z += b.z; v.w += b.w;
                        if (arelu) {
                            v.x = fmaxf(v.x, 0.f); v.y = fmaxf(v.y, 0.f);
                            v.z = fmaxf(v.z, 0.f); v.w = fmaxf(v.w, 0.f);
                        }
                    }
                }
                hbuf[i * 2 + 0] = __floats2half2_rn(v.x, v.y);
                hbuf[i * 2 + 1] = __floats2half2_rn(v.z, v.w);
            }
            uint4* dst = (uint4*)&As[ar][ac0];
            dst[0] = ((uint4*)hbuf)[0];
            dst[1] = ((uint4*)hbuf)[1];
        }
        {
            const __half2* wrow = Wh + (size_t)(k0 / 2 + brr) * Fout + j0;
#pragma unroll
            for (int i = 0; i < BCOLS / 4; i++) {
                int c = bgp * BCOLS + i * 4;
                *(uint4*)&Bs2[brr][c] = *(const uint4*)&wrow[c];
            }
        }
        __syncthreads();
#pragma unroll
        for (int ks = 0; ks < 2; ks++) {
            uint32_t af[MI][4], bf[NI][2];
#pragma unroll
            for (int mi = 0; mi < MI; mi++) {
                int m = m0w + mi * 16 + g;
                const uint32_t* r0 = (const uint32_t*)&As[m][ks * 16];
                const uint32_t* r1 = (const uint32_t*)&As[m + 8][ks * 16];
                af[mi][0] = r0[q];
                af[mi][1] = r1[q];
                af[mi][2] = r0[q + 4];
                af[mi][3] = r1[q + 4];
            }
#pragma unroll
            for (int ni = 0; ni < NI; ni++) {
                int c = n0w + ni * 8 + g;
                bf[ni][0] = *(const uint32_t*)&Bs2[ks * 8 + q][c];
                bf[ni][1] = *(const uint32_t*)&Bs2[ks * 8 + q + 4][c];
            }
#pragma unroll
            for (int mi = 0; mi < MI; mi++)
#pragma unroll
                for (int ni = 0; ni < NI; ni++)
                    mma_f16(acc[mi][ni], af[mi], bf[ni]);
        }
        __syncthreads();
    }
#pragma unroll
    for (int mi = 0; mi < MI; mi++) {
        int r0 = n0 + m0w + mi * 16 + g;
        int r1 = r0 + 8;
#pragma unroll
        for (int ni = 0; ni < NI; ni++) {
            int c = j0 + n0w + ni * 8 + 2 * q;
            if (r0 < N) st2(&out[(size_t)r0 * Fout + c], acc[mi][ni][0], acc[mi][ni][1]);
            if (r1 < N) st2(&out[(size_t)r1 * Fout + c], acc[mi][ni][2], acc[mi][ni][3]);
        }
    }
    if (asrc) {
        int hh = (j0 + n0w) >> 6;
        float as_[4][2], ad_[4][2];
#pragma unroll
        for (int ni = 0; ni < NI; ni++) {
            int cc = ((j0 + n0w + ni * 8 + 2 * q) & 63);
            as_[ni][0] = asrc[hh * 64 + cc];
            as_[ni][1] = asrc[hh * 64 + cc + 1];
            ad_[ni][0] = adst[hh * 64 + cc];
            ad_[ni][1] = adst[hh * 64 + cc + 1];
        }
#pragma unroll
        for (int mi = 0; mi < MI; mi++) {
            float s0 = 0.f, d0 = 0.f, s1 = 0.f, d1 = 0.f;
#pragma unroll
            for (int ni = 0; ni < NI; ni++) {
                s0 += acc[mi][ni][0] * as_[ni][0] + acc[mi][ni][1] * as_[ni][1];
                d0 += acc[mi][ni][0] * ad_[ni][0] + acc[mi][ni][1] * ad_[ni][1];
                s1 += acc[mi][ni][2] * as_[ni][0] + acc[mi][ni][3] * as_[ni][1];
                d1 += acc[mi][ni][2] * ad_[ni][0] + acc[mi][ni][3] * ad_[ni][1];
            }
#pragma unroll
            for (int off = 1; off <= 2; off <<= 1) {
                s0 += __shfl_xor_sync(0xFFFFFFFFu, s0, off);
                d0 += __shfl_xor_sync(0xFFFFFFFFu, d0, off);
                s1 += __shfl_xor_sync(0xFFFFFFFFu, s1, off);
                d1 += __shfl_xor_sync(0xFFFFFFFFu, d1, off);
            }
            if (q == 0) {
                int r0 = n0 + m0w + mi * 16 + g;
                int r1 = r0 + 8;
                if (r0 < N) { atomicAdd(&als[r0 * Hn + hh], s0);
                              atomicAdd(&ald[r0 * Hn + hh], d0); }
                if (r1 < N) { atomicAdd(&als[r1 * Hn + hh], s1);
                              atomicAdd(&ald[r1 * Hn + hh], d1); }
            }
        }
    }
}

template <typename TI, typename TO>
static void launch_gemm(const TI* X, const __half2* Wh, TO* out,
                        int N, int Fin, int Fout, const float* abias, int arelu,
                        const float* asrc, const float* adst,
                        float* als, float* ald) {
    int Hn = Fout / 64;
    if (Fout % 128 == 0) {
        dim3 grid(cdiv(N, 128), Fout / 128);
        hgemm<TI, TO, 128, 2, 4, 4><<<grid, 256>>>(X, Wh, out, N, Fin, Fout, abias,
                                                   arelu, asrc, adst, als, ald, Hn);
    } else {
        dim3 grid(cdiv(N, 128), Fout / 64);
        hgemm<TI, TO, 64, 4, 2, 2><<<grid, 256>>>(X, Wh, out, N, Fin, Fout, abias,
                                                  arelu, asrc, adst, als, ald, Hn);
    }
}

// ---------------- fused GAT helpers ------------------------------------------
__device__ __forceinline__ float lrelu(float x) { return (x > 0.f) ? x : 0.2f * x; }

__device__ __forceinline__ void softstep(float m, float e, float& s, float& p, float& mn) {
    float d = m - e;
    float ex = __expf(-fabsf(d));
    s = (d < 0.f) ? ex : 1.f;
    p = (d < 0.f) ? 1.f : ex;
    mn = fmaxf(m, e);
}

__device__ __forceinline__ float sel4(float4 a, int h) {
    float lo = (h & 1) ? a.y : a.x;
    float hi = (h & 1) ? a.w : a.z;
    return (h & 2) ? hi : lo;
}

// ---- H=4, lane-sliced: lane i owns 8 contiguous halves of head i/8 ----------
__global__ void gat4_sliced(const int* __restrict__ rowptr, const int* __restrict__ csrc,
                            const __half* __restrict__ hlin,
                            const float* __restrict__ als, const float* __restrict__ ald,
                            __half* __restrict__ out, int N) {
    int n = (blockIdx.x * blockDim.x + threadIdx.x) >> 5;
    int lane = threadIdx.x & 31;
    if (n >= N) return;
    const int h = lane >> 3;

    float aldv = ald[n * 4 + h];
    float4 a4 = *((const float4*)als + n);
    float m = lrelu(sel4(a4, h) + aldv);       // self loop
    float z = 1.f;

    float acc[8];
    {
        uint4 u = *(const uint4*)(hlin + (size_t)n * 256 + lane * 8);
        float2 t0 = __half22float2(*(__half2*)&u.x);
        float2 t1 = __half22float2(*(__half2*)&u.y);
        float2 t2 = __half22float2(*(__half2*)&u.z);
        float2 t3 = __half22float2(*(__half2*)&u.w);
        acc[0] = t0.x; acc[1] = t0.y; acc[2] = t1.x; acc[3] = t1.y;
        acc[4] = t2.x; acc[5] = t2.y; acc[6] = t3.x; acc[7] = t3.y;
    }

    int beg = rowptr[n], end = rowptr[n + 1];
    int src = 0; float e = 0.f;
    if (beg < end) {
        src = csrc[beg];
        float4 s4 = __ldg((const float4*)als + src);
        e = lrelu(sel4(s4, h) + aldv);
    }
    for (int k = beg; k < end; k++) {
        int csrc_cur = src; float e_cur = e;
        if (k + 1 < end) {
            src = csrc[k + 1];
            float4 s4 = __ldg((const float4*)als + src);
            e = lrelu(sel4(s4, h) + aldv);
        }
        uint4 u = *(const uint4*)(hlin + (size_t)csrc_cur * 256 + lane * 8);
        float s, p, mn;
        softstep(m, e_cur, s, p, mn);
        float2 t0 = __half22float2(*(__half2*)&u.x);
        float2 t1 = __half22float2(*(__half2*)&u.y);
        float2 t2 = __half22float2(*(__half2*)&u.z);
        float2 t3 = __half22float2(*(__half2*)&u.w);
        acc[0] = acc[0] * s + p * t0.x; acc[1] = acc[1] * s + p * t0.y;
        acc[2] = acc[2] * s + p * t1.x; acc[3] = acc[3] * s + p * t1.y;
        acc[4] = acc[4] * s + p * t2.x; acc[5] = acc[5] * s + p * t2.y;
        acc[6] = acc[6] * s + p * t3.x; acc[7] = acc[7] * s + p * t3.y;
        z = z * s + p;
        m = mn;
    }
    float inv = 1.f / (z + 1e-16f);
    uint4 o;
    *(__half2*)&o.x = __floats2half2_rn(acc[0] * inv, acc[1] * inv);
    *(__half2*)&o.y = __floats2half2_rn(acc[2] * inv, acc[3] * inv);
    *(__half2*)&o.z = __floats2half2_rn(acc[4] * inv, acc[5] * inv);
    *(__half2*)&o.w = __floats2half2_rn(acc[6] * inv, acc[7] * inv);
    *(uint4*)(out + (size_t)n * 256 + lane * 8) = o;
}

// ---- H=1 with fused mean-pool accumulate (+bias) into xg --------------------
__global__ void gat1_pool(const int* __restrict__ rowptr, const int* __restrict__ csrc,
                          const __half* __restrict__ hlin,
                          const float* __restrict__ als, const float* __restrict__ ald,
                          int N, const int* __restrict__ batch,
                          const float* __restrict__ bias, float* __restrict__ xg) {
    int n = (blockIdx.x * blockDim.x + threadIdx.x) >> 5;
    int lane = threadIdx.x & 31;
    if (n >= N) return;

    float aldv = ald[n];
    float m = lrelu(als[n] + aldv);
    float z = 1.f;
    float2 acc = __half22float2(((const __half2*)(hlin + (size_t)n * 64))[lane]);

    int beg = rowptr[n], end = rowptr[n + 1];
    int src = 0; float e = 0.f;
    if (beg < end) {
        src = csrc[beg];
        e = lrelu(als[src] + aldv);
    }
    for (int k = beg; k < end; k++) {
        int cur = src; float e_cur = e;
        if (k + 1 < end) {
            src = csrc[k + 1];
            e = lrelu(als[src] + aldv);
        }
        __half2 f = ((const __half2*)(hlin + (size_t)cur * 64))[lane];
        float s, p, mn;
        softstep(m, e_cur, s, p, mn);
        float2 fv = __half22float2(f);
        acc.x = acc.x * s + p * fv.x;
        acc.y = acc.y * s + p * fv.y;
        z = z * s + p;
        m = mn;
    }
    float inv = 1.f / (z + 1e-16f);
    int b = batch[n];
    atomicAdd(&xg[b * 64 + 2 * lane],     acc.x * inv + bias[2 * lane]);
    atomicAdd(&xg[b * 64 + 2 * lane + 1], acc.y * inv + bias[2 * lane + 1]);
}

// ---------------- pooling divide + LN ----------------------------------------
__global__ void pool_div(float* __restrict__ xg, const float* __restrict__ cnt, int B) {
    int t = blockIdx.x * blockDim.x + threadIdx.x;
    if (t >= B * 64) return;
    xg[t] /= fmaxf(cnt[t >> 6], 1.f);
}

__global__ void bias_ln(const float* __restrict__ y, const float* __restrict__ bias,
                        const float* __restrict__ g, const float* __restrict__ be,
                        float* __restrict__ out, int Fn) {
    __shared__ float red[256];
    int b = blockIdx.x, j = threadIdx.x;
    float v = y[(size_t)b * Fn + j] + bias[j];
    red[j] = v; __syncthreads();
#pragma unroll
    for (int s = 128; s > 0; s >>= 1) { if (j < s) red[j] += red[j + s]; __syncthreads(); }
    float mu = red[0] * (1.f / 256.f);
    __syncthreads();
    float dv = v - mu;
    red[j] = dv * dv; __syncthreads();
#pragma unroll
    for (int s = 128; s > 0; s >>= 1) { if (j < s) red[j] += red[j + s]; __syncthreads(); }
    float var = red[0] * (1.f / 256.f);
    out[(size_t)b * Fn + j] = dv * rsqrtf(var + 1e-5f) * g[j] + be[j];
}

// ---------------- host orchestration ---------------------------------------
extern "C" void kernel_launch(void* const* d_in, const int* in_sizes, int n_in,
                              void* d_out, int out_size) {
    const float* x      = (const float*)d_in[0];
    const void*  ei_raw = d_in[1];
    const void*  b_raw  = d_in[2];
    const float* W1  = (const float*)d_in[3];
    const float* as1 = (const float*)d_in[4];
    const float* ad1 = (const float*)d_in[5];
    const float* b1  = (const float*)d_in[6];
    const float* W2  = (const float*)d_in[7];
    const float* as2 = (const float*)d_in[8];
    const float* ad2 = (const float*)d_in[9];
    const float* b2  = (const float*)d_in[10];
    const float* W3  = (const float*)d_in[11];
    const float* as3 = (const float*)d_in[12];
    const float* ad3 = (const float*)d_in[13];
    const float* b3  = (const float*)d_in[14];
    const float* Wm1 = (const float*)d_in[15];
    const float* bm1 = (const float*)d_in[16];
    const float* Wm2 = (const float*)d_in[17];
    const float* bm2 = (const float*)d_in[18];
    const float* g2  = (const float*)d_in[19];
    const float* be2 = (const float*)d_in[20];

    int N = in_sizes[0] / 32;
    int E = in_sizes[1] / 2;
    int B = out_size / 256;

    __half *hA, *hB;
    __half2 *Wh;
    float *als, *ald, *xg, *cnt, *y1, *y2;
    int *srcA, *dstA, *batch, *deg, *excl, *bsum, *rowptr, *cursor, *csrc;
    cudaGetSymbolAddress((void**)&hA,   g_hA);
    cudaGetSymbolAddress((void**)&hB,   g_hB);
    cudaGetSymbolAddress((void**)&Wh,   g_Wh);
    cudaGetSymbolAddress((void**)&als,  g_als);
    cudaGetSymbolAddress((void**)&ald,  g_ald);
    cudaGetSymbolAddress((void**)&xg,   g_xg);
    cudaGetSymbolAddress((void**)&cnt,  g_cnt);
    cudaGetSymbolAddress((void**)&y1,   g_y1);
    cudaGetSymbolAddress((void**)&y2,   g_y2);
    cudaGetSymbolAddress((void**)&srcA, g_src);
    cudaGetSymbolAddress((void**)&dstA, g_dst);
    cudaGetSymbolAddress((void**)&batch, g_batch);
    cudaGetSymbolAddress((void**)&deg,  g_deg);
    cudaGetSymbolAddress((void**)&excl, g_excl);
    cudaGetSymbolAddress((void**)&bsum, g_bsum);
    cudaGetSymbolAddress((void**)&rowptr, g_rowptr);
    cudaGetSymbolAddress((void**)&cursor, g_cursor);
    cudaGetSymbolAddress((void**)&csrc, g_csrc);

    // dtype probe, weight preconversion, zeroing, index conversions (round-14)
    detect_dtype<<<1, 256>>>(ei_raw, E, N);
    convert_all_w<<<cdiv(WTOTAL, 256), 256>>>(W1, W2, W3, Wm1, Wm2, Wh);
    cudaMemsetAsync(deg, 0, (size_t)N * sizeof(int));
    cudaMemsetAsync(cnt, 0, (size_t)B * sizeof(float));
    cudaMemsetAsync(xg, 0, (size_t)B * 64 * sizeof(float));
    cudaMemsetAsync(als, 0, (size_t)N * 4 * sizeof(float));
    cudaMemsetAsync(ald, 0, (size_t)N * 4 * sizeof(float));
    convert_ei<<<cdiv(E, 256), 256>>>(ei_raw, srcA, dstA, deg, E);
    convert_batch<<<cdiv(N, 256), 256>>>(b_raw, batch, cnt, N);

    // conv1 GEMM
    launch_gemm<float, __half>(x, Wh + WOFF_W1, hA, N, 32, 256, nullptr, 0,
                               as1, ad1, als, ald);

    // CSR by dst
    int nb = cdiv(N, SCAN_T);
    scan1<<<nb, SCAN_T>>>(deg, excl, bsum, N);
    scan2<<<1, SCAN_T>>>(bsum, nb);
    scan3<<<cdiv(N + 1, 256), 256>>>(excl, bsum, rowptr, cursor, N, E);
    scatter_kernel<<<cdiv(E, 256), 256>>>(srcA, dstA, cursor, csrc, E);

    // conv1 aggregate (lane-sliced)
    gat4_sliced<<<cdiv((long long)N * 32, 256), 256>>>(rowptr, csrc, hA, als, ald, hB, N);
    // conv2
    cudaMemsetAsync(als, 0, (size_t)N * 4 * sizeof(float));
    cudaMemsetAsync(ald, 0, (size_t)N * 4 * sizeof(float));
    launch_gemm<__half, __half>(hB, Wh + WOFF_W2, hA, N, 256, 256, b1, 1,
                                as2, ad2, als, ald);
    gat4_sliced<<<cdiv((long long)N * 32, 256), 256>>>(rowptr, csrc, hA, als, ald, hB, N);
    // conv3 (H=1) + fused mean-pool accumulate (+b3)
    cudaMemsetAsync(als, 0, (size_t)N * sizeof(float));
    cudaMemsetAsync(ald, 0, (size_t)N * sizeof(float));
    launch_gemm<__half, __half>(hB, Wh + WOFF_W3, hA, N, 256, 64, b2, 1,
                                as3, ad3, als, ald);
    gat1_pool<<<cdiv((long long)N * 32, 256), 256>>>(rowptr, csrc, hA, als, ald,
                                                     N, batch, b3, xg);
    pool_div<<<cdiv(B * 64, 256), 256>>>(xg, cnt, B);

    // MLP head (fp32 in/out)
    launch_gemm<float, float>(xg, Wh + WOFF_WM1, y1, B, 64, 256, nullptr, 0,
                              nullptr, nullptr, nullptr, nullptr);
    launch_gemm<float, float>(y1, Wh + WOFF_WM2, y2, B, 256, 256, bm1, 1,
                              nullptr, nullptr, nullptr, nullptr);
    bias_ln<<<B, 256>>>(y2, bm2, g2, be2, (float*)d_out, 256);
}

// round 17
// speedup vs baseline: 1.2177x; 1.0231x over previous
#include <cuda_runtime.h>
#include <cuda_fp16.h>
#include <math.h>
#include <stdint.h>

#define MAXN 50000
#define MAXE 500000
#define HMAX 4
#define HC_MAX 256
#define BMAX 1000
#define SCAN_T 1024

// ---------------- scratch ----------------------------------------------------
static __device__ __align__(16) __half g_hA[(size_t)MAXN * HC_MAX];
static __device__ __align__(16) __half g_hB[(size_t)MAXN * HC_MAX];
static __device__ __align__(16) float g_als[(size_t)MAXN * HMAX];
static __device__ __align__(16) float g_ald[(size_t)MAXN * HMAX];
static __device__ __align__(16) float g_xg[(size_t)BMAX * 64];
static __device__ float g_cnt[BMAX];
static __device__ __align__(16) float g_y1[(size_t)BMAX * 256];
static __device__ __align__(16) float g_y2[(size_t)BMAX * 256];
static __device__ int   g_src[MAXE];
static __device__ int   g_dst[MAXE];
static __device__ int   g_batch[MAXN];
static __device__ int   g_deg[MAXN];
static __device__ int   g_excl[MAXN];
static __device__ int   g_bsum[SCAN_T];
static __device__ int   g_rowptr[MAXN + 1];
static __device__ int   g_cursor[MAXN];
static __device__ int   g_csrc[MAXE];
static __device__ int   g_is64;

// Pre-interleaved half2 weights: [Fin/2][Fout], entry = {W[2k][n], W[2k+1][n]}.
#define WOFF_W1  0
#define WOFF_W2  4096
#define WOFF_W3  36864
#define WOFF_WM1 45056
#define WOFF_WM2 53248
#define WTOTAL   86016
static __device__ __align__(16) __half2 g_Wh[WTOTAL];

static inline int cdiv(long long a, long long b) { return (int)((a + b - 1) / b); }

// ---------------- dtype probe (parallel) --------------------------------------
__global__ void detect_dtype(const void* ei_raw, int E, int N) {
    __shared__ int bad_s;
    if (threadIdx.x == 0) bad_s = 0;
    __syncthreads();
    const long long* p = (const long long*)ei_raw;
    int k = E < 256 ? E : 256;
    bool bad = false;
    for (int j = threadIdx.x; j < k; j += 256) {
        long long v = p[j];
        if (v < 0 || v >= N) bad = true;
    }
    if (bad) atomicOr(&bad_s, 1);
    __syncthreads();
    if (threadIdx.x == 0) g_is64 = bad_s ? 0 : 1;
}

__global__ void convert_ei(const void* ei_raw, int* __restrict__ src,
                           int* __restrict__ dst, int* __restrict__ deg, int E) {
    int i = blockIdx.x * blockDim.x + threadIdx.x;
    if (i >= E) return;
    int s, d;
    if (g_is64) {
        const long long* p = (const long long*)ei_raw;
        s = (int)p[i]; d = (int)p[E + i];
    } else {
        const int* p = (const int*)ei_raw;
        s = p[i]; d = p[E + i];
    }
    src[i] = s; dst[i] = d;
    atomicAdd(&deg[d], 1);
}

// convert batch + warp-aggregated counts (batch is sorted by construction)
__global__ void convert_batch(const void* b_raw, int* __restrict__ out,
                              float* __restrict__ cnt, int N) {
    int i = blockIdx.x * blockDim.x + threadIdx.x;
    if (i >= N) return;
    int b;
    if (g_is64) b = (int)((const long long*)b_raw)[i];
    else        b = ((const int*)b_raw)[i];
    out[i] = b;
    unsigned act = __activemask();
    unsigned mask = __match_any_sync(act, b);
    int leader = __ffs(mask) - 1;
    if ((int)(threadIdx.x & 31) == leader)
        atomicAdd(&cnt[b], (float)__popc(mask));
}

// One-shot: convert all weight matrices to interleaved half2.
__global__ void convert_all_w(const float* __restrict__ W1, const float* __restrict__ W2,
                              const float* __restrict__ W3, const float* __restrict__ Wm1,
                              const float* __restrict__ Wm2, __half2* __restrict__ out) {
    int i = blockIdx.x * blockDim.x + threadIdx.x;
    if (i >= WTOTAL) return;
    const float* W; int Fout, base;
    if (i < WOFF_W2)       { W = W1;  Fout = 256; base = WOFF_W1; }
    else if (i < WOFF_W3)  { W = W2;  Fout = 256; base = WOFF_W2; }
    else if (i < WOFF_WM1) { W = W3;  Fout = 64;  base = WOFF_W3; }
    else if (i < WOFF_WM2) { W = Wm1; Fout = 256; base = WOFF_WM1; }
    else                   { W = Wm2; Fout = 256; base = WOFF_WM2; }
    int j = i - base;
    int kp = j / Fout, n = j - kp * Fout;
    out[i] = __floats2half2_rn(W[(size_t)(2 * kp) * Fout + n],
                               W[(size_t)(2 * kp + 1) * Fout + n]);
}

// ---------------- CSR build (3-stage scan) -------------------------------------
__global__ void scan1(const int* __restrict__ deg, int* __restrict__ excl,
                      int* __restrict__ bsum, int n) {
    __shared__ int s[SCAN_T];
    int i = blockIdx.x * SCAN_T + threadIdx.x;
    int v = (i < n) ? deg[i] : 0;
    s[threadIdx.x] = v; __syncthreads();
    for (int off = 1; off < SCAN_T; off <<= 1) {
        int t = (threadIdx.x >= off) ? s[threadIdx.x - off] : 0;
        __syncthreads();
        s[threadIdx.x] += t;
        __syncthreads();
    }
    if (i < n) excl[i] = s[threadIdx.x] - v;
    if (threadIdx.x == SCAN_T - 1) bsum[blockIdx.x] = s[SCAN_T - 1];
}

__global__ void scan2(int* __restrict__ bsum, int nb) {
    __shared__ int s[SCAN_T];
    int v = (threadIdx.x < nb) ? bsum[threadIdx.x] : 0;
    s[threadIdx.x] = v; __syncthreads();
    for (int off = 1; off < SCAN_T; off <<= 1) {
        int t = (threadIdx.x >= off) ? s[threadIdx.x - off] : 0;
        __syncthreads();
        s[threadIdx.x] += t;
        __syncthreads();
    }
    if (threadIdx.x < nb) bsum[threadIdx.x] = s[threadIdx.x] - v;
}

__global__ void scan3(const int* __restrict__ excl, const int* __restrict__ bsum,
                      int* __restrict__ rowptr, int* __restrict__ cursor, int n, int E) {
    int i = blockIdx.x * blockDim.x + threadIdx.x;
    if (i < n) { int r = excl[i] + bsum[i / SCAN_T]; rowptr[i] = r; cursor[i] = r; }
    if (i == 0) rowptr[n] = E;
}

__global__ void scatter_kernel(const int* __restrict__ srcA, const int* __restrict__ dstA,
                               int* __restrict__ cursor, int* __restrict__ csrc, int E) {
    int i = blockIdx.x * blockDim.x + threadIdx.x;
    if (i >= E) return;
    int pos = atomicAdd(&cursor[dstA[i]], 1);
    csrc[pos] = srcA[i];
}

// ---------------- FP16 tensor-core GEMM (m16n8k16, fp32 accum) ---------------
__device__ __forceinline__ void mma_f16(float* c, const uint32_t* a, const uint32_t* b) {
    asm volatile(
        "mma.sync.aligned.m16n8k16.row.col.f32.f16.f16.f32 "
        "{%0,%1,%2,%3}, {%4,%5,%6,%7}, {%8,%9}, {%0,%1,%2,%3};"
        : "+f"(c[0]), "+f"(c[1]), "+f"(c[2]), "+f"(c[3])
        : "r"(a[0]), "r"(a[1]), "r"(a[2]), "r"(a[3]), "r"(b[0]), "r"(b[1]));
}

__device__ __forceinline__ float4 ld4(const float* p) { return *(const float4*)p; }
__device__ __forceinline__ float4 ld4(const __half* p) {
    const __half2* h = (const __half2*)p;
    float2 a = __half22float2(h[0]), b = __half22float2(h[1]);
    return make_float4(a.x, a.y, b.x, b.y);
}
__device__ __forceinline__ void st2(float* p, float a, float b) {
    *(float2*)p = make_float2(a, b);
}
__device__ __forceinline__ void st2(__half* p, float a, float b) {
    *(__half2*)p = __floats2half2_rn(a, b);
}

template <typename TI, typename TO, int BN, int WR, int WC, int MI>
__global__ void __launch_bounds__(256)
hgemm(const TI* __restrict__ X, const __half2* __restrict__ Wh,
      TO* __restrict__ out, int N, int Fin, int Fout,
      const float* __restrict__ abias, int arelu,
      const float* __restrict__ asrc, const float* __restrict__ adst,
      float* __restrict__ als, float* __restrict__ ald, int Hn) {
    constexpr int BM = 128, BK = 32, NI = 4;
    constexpr int WM = BM / WR;
    constexpr int WN = BN / WC;
    constexpr int AP = BK + 8;
    constexpr int BP = BN + 4;
    __shared__ __half  As[BM][AP];
    __shared__ __half2 Bs2[BK / 2][BP];
    const int tx = threadIdx.x;
    const int n0 = blockIdx.x * BM;
    const int j0 = blockIdx.y * BN;
    const int w  = tx >> 5;
    const int lane = tx & 31;
    const int g = lane >> 2;
    const int q = lane & 3;
    const int wr = w / WC, wc = w % WC;
    const int m0w = wr * WM, n0w = wc * WN;

    float acc[MI][NI][4];
#pragma unroll
    for (int mi = 0; mi < MI; mi++)
#pragma unroll
        for (int ni = 0; ni < NI; ni++)
#pragma unroll
            for (int t = 0; t < 4; t++) acc[mi][ni][t] = 0.f;

    const int ar  = tx >> 1;
    const int ac0 = (tx & 1) * 16;
    const int brr = tx & 15;
    const int bgp = tx >> 4;
    constexpr int BCOLS = BN / 16;

    for (int k0 = 0; k0 < Fin; k0 += BK) {
        {
            int n = n0 + ar;
            __half2 hbuf[8];
#pragma unroll
            for (int i = 0; i < 4; i++) {
                int c = ac0 + i * 4;
                float4 v = make_float4(0.f, 0.f, 0.f, 0.f);
                if (n < N) {
                    v = ld4(&X[(size_t)n * Fin + k0 + c]);
                    if (abias) {
                        const float4 b = *(const float4*)&abias[k0 + c];
                        v.x += b.x; v.y += b.y; v.z += b.z; v.w += b.w;
                        if (arelu) {
                            v.x = fmaxf(v.x, 0.f); v.y = fmaxf(v.y, 0.f);
                            v.z = fmaxf(v.z, 0.f); v.w = fmaxf(v.w, 0.f);
                        }
                    }
                }
                hbuf[i * 2 + 0] = __floats2half2_rn(v.x, v.y);
                hbuf[i * 2 + 1] = __floats2half2_rn(v.z, v.w);
            }
            uint4* dst = (uint4*)&As[ar][ac0];
            dst[0] = ((uint4*)hbuf)[0];
            dst[1] = ((uint4*)hbuf)[1];
        }
        {
            const __half2* wrow = Wh + (size_t)(k0 / 2 + brr) * Fout + j0;
#pragma unroll
            for (int i = 0; i < BCOLS / 4; i++) {
                int c = bgp * BCOLS + i * 4;
                *(uint4*)&Bs2[brr][c] = *(const uint4*)&wrow[c];
            }
        }
        __syncthreads();
#pragma unroll
        for (int ks = 0; ks < 2; ks++) {
            uint32_t af[MI][4], bf[NI][2];
#pragma unroll
            for (int mi = 0; mi < MI; mi++) {
                int m = m0w + mi * 16 + g;
                const uint32_t* r0 = (const uint32_t*)&As[m][ks * 16];
                const uint32_t* r1 = (const uint32_t*)&As[m + 8][ks * 16];
                af[mi][0] = r0[q];
                af[mi][1] = r1[q];
                af[mi][2] = r0[q + 4];
                af[mi][3] = r1[q + 4];
            }
#pragma unroll
            for (int ni = 0; ni < NI; ni++) {
                int c = n0w + ni * 8 + g;
                bf[ni][0] = *(const uint32_t*)&Bs2[ks * 8 + q][c];
                bf[ni][1] = *(const uint32_t*)&Bs2[ks * 8 + q + 4][c];
            }
#pragma unroll
            for (int mi = 0; mi < MI; mi++)
#pragma unroll
                for (int ni = 0; ni < NI; ni++)
                    mma_f16(acc[mi][ni], af[mi], bf[ni]);
        }
        __syncthreads();
    }
#pragma unroll
    for (int mi = 0; mi < MI; mi++) {
        int r0 = n0 + m0w + mi * 16 + g;
        int r1 = r0 + 8;
#pragma unroll
        for (int ni = 0; ni < NI; ni++) {
            int c = j0 + n0w + ni * 8 + 2 * q;
            if (r0 < N) st2(&out[(size_t)r0 * Fout + c], acc[mi][ni][0], acc[mi][ni][1]);
            if (r1 < N) st2(&out[(size_t)r1 * Fout + c], acc[mi][ni][2], acc[mi][ni][3]);
        }
    }
    if (asrc) {
        int hh = (j0 + n0w) >> 6;
        float as_[4][2], ad_[4][2];
#pragma unroll
        for (int ni = 0; ni < NI; ni++) {
            int cc = ((j0 + n0w + ni * 8 + 2 * q) & 63);
            as_[ni][0] = asrc[hh * 64 + cc];
            as_[ni][1] = asrc[hh * 64 + cc + 1];
            ad_[ni][0] = adst[hh * 64 + cc];
            ad_[ni][1] = adst[hh * 64 + cc + 1];
        }
#pragma unroll
        for (int mi = 0; mi < MI; mi++) {
            float s0 = 0.f, d0 = 0.f, s1 = 0.f, d1 = 0.f;
#pragma unroll
            for (int ni = 0; ni < NI; ni++) {
                s0 += acc[mi][ni][0] * as_[ni][0] + acc[mi][ni][1] * as_[ni][1];
                d0 += acc[mi][ni][0] * ad_[ni][0] + acc[mi][ni][1] * ad_[ni][1];
                s1 += acc[mi][ni][2] * as_[ni][0] + acc[mi][ni][3] * as_[ni][1];
                d1 += acc[mi][ni][2] * ad_[ni][0] + acc[mi][ni][3] * ad_[ni][1];
            }
#pragma unroll
            for (int off = 1; off <= 2; off <<= 1) {
                s0 += __shfl_xor_sync(0xFFFFFFFFu, s0, off);
                d0 += __shfl_xor_sync(0xFFFFFFFFu, d0, off);
                s1 += __shfl_xor_sync(0xFFFFFFFFu, s1, off);
                d1 += __shfl_xor_sync(0xFFFFFFFFu, d1, off);
            }
            if (q == 0) {
                int r0 = n0 + m0w + mi * 16 + g;
                int r1 = r0 + 8;
                if (r0 < N) { atomicAdd(&als[r0 * Hn + hh], s0);
                              atomicAdd(&ald[r0 * Hn + hh], d0); }
                if (r1 < N) { atomicAdd(&als[r1 * Hn + hh], s1);
                              atomicAdd(&ald[r1 * Hn + hh], d1); }
            }
        }
    }
}

template <typename TI, typename TO>
static void launch_gemm(const TI* X, const __half2* Wh, TO* out,
                        int N, int Fin, int Fout, const float* abias, int arelu,
                        const float* asrc, const float* adst,
                        float* als, float* ald, cudaStream_t st = 0) {
    int Hn = Fout / 64;
    if (Fout % 128 == 0) {
        dim3 grid(cdiv(N, 128), Fout / 128);
        hgemm<TI, TO, 128, 2, 4, 4><<<grid, 256, 0, st>>>(X, Wh, out, N, Fin, Fout, abias,
                                                          arelu, asrc, adst, als, ald, Hn);
    } else {
        dim3 grid(cdiv(N, 128), Fout / 64);
        hgemm<TI, TO, 64, 4, 2, 2><<<grid, 256, 0, st>>>(X, Wh, out, N, Fin, Fout, abias,
                                                         arelu, asrc, adst, als, ald, Hn);
    }
}

// ---------------- fused GAT helpers ------------------------------------------
__device__ __forceinline__ float lrelu(float x) { return (x > 0.f) ? x : 0.2f * x; }

__device__ __forceinline__ void softstep(float m, float e, float& s, float& p, float& mn) {
    float d = m - e;
    float ex = __expf(-fabsf(d));
    s = (d < 0.f) ? ex : 1.f;
    p = (d < 0.f) ? 1.f : ex;
    mn = fmaxf(m, e);
}

__device__ __forceinline__ float sel4(float4 a, int h) {
    float lo = (h & 1) ? a.y : a.x;
    float hi = (h & 1) ? a.w : a.z;
    return (h & 2) ? hi : lo;
}

// ---- H=4, lane-sliced ---------------------------------------------------------
__global__ void gat4_sliced(const int* __restrict__ rowptr, const int* __restrict__ csrc,
                            const __half* __restrict__ hlin,
                            const float* __restrict__ als, const float* __restrict__ ald,
                            __half* __restrict__ out, int N) {
    int n = (blockIdx.x * blockDim.x + threadIdx.x) >> 5;
    int lane = threadIdx.x & 31;
    if (n >= N) return;
    const int h = lane >> 3;

    float aldv = ald[n * 4 + h];
    float4 a4 = *((const float4*)als + n);
    float m = lrelu(sel4(a4, h) + aldv);
    float z = 1.f;

    float acc[8];
    {
        uint4 u = *(const uint4*)(hlin + (size_t)n * 256 + lane * 8);
        float2 t0 = __half22float2(*(__half2*)&u.x);
        float2 t1 = __half22float2(*(__half2*)&u.y);
        float2 t2 = __half22float2(*(__half2*)&u.z);
        float2 t3 = __half22float2(*(__half2*)&u.w);
        acc[0] = t0.x; acc[1] = t0.y; acc[2] = t1.x; acc[3] = t1.y;
        acc[4] = t2.x; acc[5] = t2.y; acc[6] = t3.x; acc[7] = t3.y;
    }

    int beg = rowptr[n], end = rowptr[n + 1];
    int src = 0; float e = 0.f;
    if (beg < end) {
        src = csrc[beg];
        float4 s4 = __ldg((const float4*)als + src);
        e = lrelu(sel4(s4, h) + aldv);
    }
    for (int k = beg; k < end; k++) {
        int csrc_cur = src; float e_cur = e;
        if (k + 1 < end) {
            src = csrc[k + 1];
            float4 s4 = __ldg((const float4*)als + src);
            e = lrelu(sel4(s4, h) + aldv);
        }
        uint4 u = *(const uint4*)(hlin + (size_t)csrc_cur * 256 + lane * 8);
        float s, p, mn;
        softstep(m, e_cur, s, p, mn);
        float2 t0 = __half22float2(*(__half2*)&u.x);
        float2 t1 = __half22float2(*(__half2*)&u.y);
        float2 t2 = __half22float2(*(__half2*)&u.z);
        float2 t3 = __half22float2(*(__half2*)&u.w);
        acc[0] = acc[0] * s + p * t0.x; acc[1] = acc[1] * s + p * t0.y;
        acc[2] = acc[2] * s + p * t1.x; acc[3] = acc[3] * s + p * t1.y;
        acc[4] = acc[4] * s + p * t2.x; acc[5] = acc[5] * s + p * t2.y;
        acc[6] = acc[6] * s + p * t3.x; acc[7] = acc[7] * s + p * t3.y;
        z = z * s + p;
        m = mn;
    }
    float inv = 1.f / (z + 1e-16f);
    uint4 o;
    *(__half2*)&o.x = __floats2half2_rn(acc[0] * inv, acc[1] * inv);
    *(__half2*)&o.y = __floats2half2_rn(acc[2] * inv, acc[3] * inv);
    *(__half2*)&o.z = __floats2half2_rn(acc[4] * inv, acc[5] * inv);
    *(__half2*)&o.w = __floats2half2_rn(acc[6] * inv, acc[7] * inv);
    *(uint4*)(out + (size_t)n * 256 + lane * 8) = o;
}

// ---- H=1 with fused mean-pool accumulate (+bias) into xg --------------------
__global__ void gat1_pool(const int* __restrict__ rowptr, const int* __restrict__ csrc,
                          const __half* __restrict__ hlin,
                          const float* __restrict__ als, const float* __restrict__ ald,
                          int N, const int* __restrict__ batch,
                          const float* __restrict__ bias, float* __restrict__ xg) {
    int n = (blockIdx.x * blockDim.x + threadIdx.x) >> 5;
    int lane = threadIdx.x & 31;
    if (n >= N) return;

    float aldv = ald[n];
    float m = lrelu(als[n] + aldv);
    float z = 1.f;
    float2 acc = __half22float2(((const __half2*)(hlin + (size_t)n * 64))[lane]);

    int beg = rowptr[n], end = rowptr[n + 1];
    int src = 0; float e = 0.f;
    if (beg < end) {
        src = csrc[beg];
        e = lrelu(als[src] + aldv);
    }
    for (int k = beg; k < end; k++) {
        int cur = src; float e_cur = e;
        if (k + 1 < end) {
            src = csrc[k + 1];
            e = lrelu(als[src] + aldv);
        }
        __half2 f = ((const __half2*)(hlin + (size_t)cur * 64))[lane];
        float s, p, mn;
        softstep(m, e_cur, s, p, mn);
        float2 fv = __half22float2(f);
        acc.x = acc.x * s + p * fv.x;
        acc.y = acc.y * s + p * fv.y;
        z = z * s + p;
        m = mn;
    }
    float inv = 1.f / (z + 1e-16f);
    int b = batch[n];
    atomicAdd(&xg[b * 64 + 2 * lane],     acc.x * inv + bias[2 * lane]);
    atomicAdd(&xg[b * 64 + 2 * lane + 1], acc.y * inv + bias[2 * lane + 1]);
}

// ---------------- pooling divide + LN ----------------------------------------
__global__ void pool_div(float* __restrict__ xg, const float* __restrict__ cnt, int B) {
    int t = blockIdx.x * blockDim.x + threadIdx.x;
    if (t >= B * 64) return;
    xg[t] /= fmaxf(cnt[t >> 6], 1.f);
}

__global__ void bias_ln(const float* __restrict__ y, const float* __restrict__ bias,
                        const float* __restrict__ g, const float* __restrict__ be,
                        float* __restrict__ out, int Fn) {
    __shared__ float red[256];
    int b = blockIdx.x, j = threadIdx.x;
    float v = y[(size_t)b * Fn + j] + bias[j];
    red[j] = v; __syncthreads();
#pragma unroll
    for (int s = 128; s > 0; s >>= 1) { if (j < s) red[j] += red[j + s]; __syncthreads(); }
    float mu = red[0] * (1.f / 256.f);
    __syncthreads();
    float dv = v - mu;
    red[j] = dv * dv; __syncthreads();
#pragma unroll
    for (int s = 128; s > 0; s >>= 1) { if (j < s) red[j] += red[j + s]; __syncthreads(); }
    float var = red[0] * (1.f / 256.f);
    out[(size_t)b * Fn + j] = dv * rsqrtf(var + 1e-5f) * g[j] + be[j];
}

// ---------------- host orchestration ---------------------------------------
extern "C" void kernel_launch(void* const* d_in, const int* in_sizes, int n_in,
                              void* d_out, int out_size) {
    const float* x      = (const float*)d_in[0];
    const void*  ei_raw = d_in[1];
    const void*  b_raw  = d_in[2];
    const float* W1  = (const float*)d_in[3];
    const float* as1 = (const float*)d_in[4];
    const float* ad1 = (const float*)d_in[5];
    const float* b1  = (const float*)d_in[6];
    const float* W2  = (const float*)d_in[7];
    const float* as2 = (const float*)d_in[8];
    const float* ad2 = (const float*)d_in[9];
    const float* b2  = (const float*)d_in[10];
    const float* W3  = (const float*)d_in[11];
    const float* as3 = (const float*)d_in[12];
    const float* ad3 = (const float*)d_in[13];
    const float* b3  = (const float*)d_in[14];
    const float* Wm1 = (const float*)d_in[15];
    const float* bm1 = (const float*)d_in[16];
    const float* Wm2 = (const float*)d_in[17];
    const float* bm2 = (const float*)d_in[18];
    const float* g2  = (const float*)d_in[19];
    const float* be2 = (const float*)d_in[20];

    int N = in_sizes[0] / 32;
    int E = in_sizes[1] / 2;
    int B = out_size / 256;

    __half *hA, *hB;
    __half2 *Wh;
    float *als, *ald, *xg, *cnt, *y1, *y2;
    int *srcA, *dstA, *batch, *deg, *excl, *bsum, *rowptr, *cursor, *csrc;
    cudaGetSymbolAddress((void**)&hA,   g_hA);
    cudaGetSymbolAddress((void**)&hB,   g_hB);
    cudaGetSymbolAddress((void**)&Wh,   g_Wh);
    cudaGetSymbolAddress((void**)&als,  g_als);
    cudaGetSymbolAddress((void**)&ald,  g_ald);
    cudaGetSymbolAddress((void**)&xg,   g_xg);
    cudaGetSymbolAddress((void**)&cnt,  g_cnt);
    cudaGetSymbolAddress((void**)&y1,   g_y1);
    cudaGetSymbolAddress((void**)&y2,   g_y2);
    cudaGetSymbolAddress((void**)&srcA, g_src);
    cudaGetSymbolAddress((void**)&dstA, g_dst);
    cudaGetSymbolAddress((void**)&batch, g_batch);
    cudaGetSymbolAddress((void**)&deg,  g_deg);
    cudaGetSymbolAddress((void**)&excl, g_excl);
    cudaGetSymbolAddress((void**)&bsum, g_bsum);
    cudaGetSymbolAddress((void**)&rowptr, g_rowptr);
    cudaGetSymbolAddress((void**)&cursor, g_cursor);
    cudaGetSymbolAddress((void**)&csrc, g_csrc);

    // Fork a side stream for the conv1-compute chain (joined via events; legal
    // inside stream capture). Created/destroyed per call (only capture +
    // correctness calls actually execute this host code).
    cudaStream_t s2;
    cudaStreamCreateWithFlags(&s2, cudaStreamNonBlocking);
    cudaEvent_t evStart, evDetect, evGemm1;
    cudaEventCreateWithFlags(&evStart,  cudaEventDisableTiming);
    cudaEventCreateWithFlags(&evDetect, cudaEventDisableTiming);
    cudaEventCreateWithFlags(&evGemm1,  cudaEventDisableTiming);

    // ---- stream 0: CSR chain ----
    cudaMemsetAsync(deg, 0, (size_t)N * sizeof(int));
    cudaEventRecord(evStart, 0);               // fork point for s2
    detect_dtype<<<1, 256>>>(ei_raw, E, N);
    cudaEventRecord(evDetect, 0);
    convert_ei<<<cdiv(E, 256), 256>>>(ei_raw, srcA, dstA, deg, E);
    int nb = cdiv(N, SCAN_T);
    scan1<<<nb, SCAN_T>>>(deg, excl, bsum, N);
    scan2<<<1, SCAN_T>>>(bsum, nb);
    scan3<<<cdiv(N + 1, 256), 256>>>(excl, bsum, rowptr, cursor, N, E);
    scatter_kernel<<<cdiv(E, 256), 256>>>(srcA, dstA, cursor, csrc, E);

    // ---- stream s2: weights + zeroing + conv1 GEMM + batch conversion ----
    cudaStreamWaitEvent(s2, evStart, 0);
    convert_all_w<<<cdiv(WTOTAL, 256), 256, 0, s2>>>(W1, W2, W3, Wm1, Wm2, Wh);
    cudaMemsetAsync(als, 0, (size_t)N * 4 * sizeof(float), s2);
    cudaMemsetAsync(ald, 0, (size_t)N * 4 * sizeof(float), s2);
    cudaMemsetAsync(xg, 0, (size_t)B * 64 * sizeof(float), s2);
    cudaMemsetAsync(cnt, 0, (size_t)B * sizeof(float), s2);
    launch_gemm<float, __half>(x, Wh + WOFF_W1, hA, N, 32, 256, nullptr, 0,
                               as1, ad1, als, ald, s2);
    cudaStreamWaitEvent(s2, evDetect, 0);      // convert_batch needs g_is64
    convert_batch<<<cdiv(N, 256), 256, 0, s2>>>(b_raw, batch, cnt, N);
    cudaEventRecord(evGemm1, s2);

    // ---- join: aggregation needs CSR (stream 0) + hlin/als/ald (s2) ----
    cudaStreamWaitEvent(0, evGemm1, 0);
    gat4_sliced<<<cdiv((long long)N * 32, 256), 256>>>(rowptr, csrc, hA, als, ald, hB, N);

    // conv2
    cudaMemsetAsync(als, 0, (size_t)N * 4 * sizeof(float));
    cudaMemsetAsync(ald, 0, (size_t)N * 4 * sizeof(float));
    launch_gemm<__half, __half>(hB, Wh + WOFF_W2, hA, N, 256, 256, b1, 1,
                                as2, ad2, als, ald);
    gat4_sliced<<<cdiv((long long)N * 32, 256), 256>>>(rowptr, csrc, hA, als, ald, hB, N);
    // conv3 (H=1) + fused mean-pool accumulate (+b3)
    cudaMemsetAsync(als, 0, (size_t)N * sizeof(float));
    cudaMemsetAsync(ald, 0, (size_t)N * sizeof(float));
    launch_gemm<__half, __half>(hB, Wh + WOFF_W3, hA, N, 256, 64, b2, 1,
                                as3, ad3, als, ald);
    gat1_pool<<<cdiv((long long)N * 32, 256), 256>>>(rowptr, csrc, hA, als, ald,
                                                     N, batch, b3, xg);
    pool_div<<<cdiv(B * 64, 256), 256>>>(xg, cnt, B);

    // MLP head (fp32 in/out)
    launch_gemm<float, float>(xg, Wh + WOFF_WM1, y1, B, 64, 256, nullptr, 0,
                              nullptr, nullptr, nullptr, nullptr);
    launch_gemm<float, float>(y1, Wh + WOFF_WM2, y2, B, 256, 256, bm1, 1,
                              nullptr, nullptr, nullptr, nullptr);
    bias_ln<<<B, 256>>>(y2, bm2, g2, be2, (float*)d_out, 256);

    cudaEventDestroy(evStart);
    cudaEventDestroy(evDetect);
    cudaEventDestroy(evGemm1);
    cudaStreamDestroy(s2);
}